// round 3
// baseline (speedup 1.0000x reference)
#include <cuda_runtime.h>
#include <math.h>

// Problem constants
#define B   2
#define T   2048
#define E   2048
#define G   4
#define QPG 4
#define D   128
#define NH  (G*QPG)     // 16 heads
#define QDIM (NH*D)     // 2048
#define KVDIM (2*G*D)   // 1024
#define MROWS (B*T)     // 4096

// Scratch (device globals: no allocations allowed)
__device__ float g_q  [MROWS * QDIM];   // q   = x@wq + bq + pe      [B*T, 2048]
__device__ float g_kv [MROWS * KVDIM];  // kv  = x@wkv + bkv (+pe on k half) [B*T, 1024]
__device__ float g_att[MROWS * QDIM];   // attention output          [B*T, 2048]
__device__ float g_pe [T * D];          // sinusoidal PE table

// ---------------------------------------------------------------------------
// PE table init (recomputed every launch — deterministic, trivial cost)
// ---------------------------------------------------------------------------
__global__ void pe_init_kernel() {
    int idx = blockIdx.x * blockDim.x + threadIdx.x;
    if (idx >= T * D) return;
    int t = idx / D, d = idx % D;
    float i2  = (float)(d & ~1);                       // 2*floor(d/2)
    float inv = expf(-(logf(10000.0f) * i2 / (float)D));
    float ang = (float)t * inv;
    g_pe[idx] = (d & 1) ? cosf(ang) : sinf(ang);
}

// ---------------------------------------------------------------------------
// Tiled SGEMM: C[M,N] = A[M,K] @ W[K,N] (+bias) (+PE per mode)
// 128x128 block tile, 8x8 per thread, K-tile 16, 256 threads.
// mode 0: plain      mode 1: +bias +pe (q proj)    mode 2: +bias +pe on k-half (kv proj)
// ---------------------------------------------------------------------------
#define TK 16
__global__ __launch_bounds__(256) void sgemm_kernel(
    const float* __restrict__ A, const float* __restrict__ W,
    const float* __restrict__ bias, float* __restrict__ C,
    int M, int N, int K, int mode)
{
    __shared__ float As[TK][132];   // stored transposed: As[k][m], padded
    __shared__ float Bs[TK][132];   // Bs[k][n], padded

    const int tid = threadIdx.x;
    const int bm = blockIdx.y * 128;
    const int bn = blockIdx.x * 128;

    // A loader: 128 rows x 16 k = 512 float4; 2 per thread
    const int a_row = tid >> 2;            // 0..63 (plus +64)
    const int a_col = (tid & 3) * 4;       // 0,4,8,12
    // B loader: 16 k rows x 128 n = 512 float4; 2 per thread
    const int b_row = tid >> 4;            // 0..15
    const int b_col = (tid & 15) * 8;      // 0..120 (two float4)

    const int tx = tid & 15, ty = tid >> 4;

    float acc[8][8];
    #pragma unroll
    for (int i = 0; i < 8; i++)
        #pragma unroll
        for (int j = 0; j < 8; j++) acc[i][j] = 0.f;

    for (int k0 = 0; k0 < K; k0 += TK) {
        // load A tile (transpose into As[k][m])
        #pragma unroll
        for (int h = 0; h < 2; h++) {
            int r = a_row + h * 64;
            float4 av = *reinterpret_cast<const float4*>(&A[(size_t)(bm + r) * K + k0 + a_col]);
            As[a_col + 0][r] = av.x;
            As[a_col + 1][r] = av.y;
            As[a_col + 2][r] = av.z;
            As[a_col + 3][r] = av.w;
        }
        // load B tile
        {
            const float* wrow = &W[(size_t)(k0 + b_row) * N + bn + b_col];
            float4 b0 = *reinterpret_cast<const float4*>(wrow);
            float4 b1 = *reinterpret_cast<const float4*>(wrow + 4);
            *reinterpret_cast<float4*>(&Bs[b_row][b_col])     = b0;
            *reinterpret_cast<float4*>(&Bs[b_row][b_col + 4]) = b1;
        }
        __syncthreads();

        #pragma unroll
        for (int kk = 0; kk < TK; kk++) {
            float ra[8], rb[8];
            *reinterpret_cast<float4*>(&ra[0]) = *reinterpret_cast<const float4*>(&As[kk][ty * 4]);
            *reinterpret_cast<float4*>(&ra[4]) = *reinterpret_cast<const float4*>(&As[kk][ty * 4 + 64]);
            *reinterpret_cast<float4*>(&rb[0]) = *reinterpret_cast<const float4*>(&Bs[kk][tx * 4]);
            *reinterpret_cast<float4*>(&rb[4]) = *reinterpret_cast<const float4*>(&Bs[kk][tx * 4 + 64]);
            #pragma unroll
            for (int i = 0; i < 8; i++)
                #pragma unroll
                for (int j = 0; j < 8; j++)
                    acc[i][j] = fmaf(ra[i], rb[j], acc[i][j]);
        }
        __syncthreads();
    }

    // epilogue
    #pragma unroll
    for (int i = 0; i < 8; i++) {
        int row = bm + ty * 4 + (i & 3) + (i >> 2) * 64;
        int t   = row & (T - 1);
        #pragma unroll
        for (int j = 0; j < 8; j++) {
            int col = bn + tx * 4 + (j & 3) + (j >> 2) * 64;
            float v = acc[i][j];
            if (mode != 0) v += bias[col];
            if (mode == 1) {
                v += g_pe[t * D + (col & (D - 1))];
            } else if (mode == 2) {
                int dc = col & (2 * D - 1);
                if (dc < D) v += g_pe[t * D + dc];
            }
            C[(size_t)row * N + col] = v;
        }
    }
}

// ---------------------------------------------------------------------------
// Flash attention (causal, online softmax). fp32.
// One CTA: 64 query rows of one head. 256 threads. Loops over 64-key tiles.
// ---------------------------------------------------------------------------
#define BR 64
#define BC 64
#define KP 132   // padded row stride for Q/K/V tiles (conflict-free)
#define SP 65    // padded row stride for score tile

struct FlashSmem {
    float Q [BR][KP];
    float Kt[BC][KP];
    float Vt[BC][KP];
    float S [BR][SP];
    float m[BR];
    float l[BR];
    float scale[BR];
};

__global__ __launch_bounds__(256) void flash_kernel(
    const float* __restrict__ Qg, const float* __restrict__ KVg, float* __restrict__ Og)
{
    extern __shared__ float smem_raw[];
    FlashSmem* sm = reinterpret_cast<FlashSmem*>(smem_raw);

    const int tid  = threadIdx.x;
    const int qb   = blockIdx.x * BR;
    const int head = blockIdx.y;        // g = head>>2, qpg = head&3
    const int b    = blockIdx.z;
    const int g    = head >> 2;

    const float* qbase  = Qg  + (size_t)b * T * QDIM  + head * D;
    const float* kvbase = KVg + (size_t)b * T * KVDIM + g * (2 * D);
    float*       obase  = Og  + (size_t)b * T * QDIM  + head * D;

    // Load Q tile: 64x128, 8 float4 per thread, coalesced
    {
        int r0 = tid >> 5;             // 0..7
        int c  = (tid & 31) * 4;       // 0..124
        #pragma unroll
        for (int i = 0; i < 8; i++) {
            int r = r0 + i * 8;
            *reinterpret_cast<float4*>(&sm->Q[r][c]) =
                *reinterpret_cast<const float4*>(&qbase[(size_t)(qb + r) * QDIM + c]);
        }
    }
    if (tid < BR) { sm->m[tid] = -INFINITY; sm->l[tid] = 0.f; }

    const int tx = tid & 15, ty = tid >> 4;

    float acc[4][8];   // rows ty+16i, cols tx+16c
    #pragma unroll
    for (int i = 0; i < 4; i++)
        #pragma unroll
        for (int c = 0; c < 8; c++) acc[i][c] = 0.f;

    const int ntiles = qb / BC + 1;

    for (int kt = 0; kt < ntiles; kt++) {
        __syncthreads();   // protect Kt/Vt/S from previous iteration consumers
        // Load K,V tiles
        {
            int r0 = tid >> 5;
            int c  = (tid & 31) * 4;
            #pragma unroll
            for (int i = 0; i < 8; i++) {
                int r = r0 + i * 8;
                const float* kvrow = &kvbase[(size_t)(kt * BC + r) * KVDIM];
                *reinterpret_cast<float4*>(&sm->Kt[r][c]) =
                    *reinterpret_cast<const float4*>(&kvrow[c]);
                *reinterpret_cast<float4*>(&sm->Vt[r][c]) =
                    *reinterpret_cast<const float4*>(&kvrow[D + c]);
            }
        }
        __syncthreads();

        // Scores: S[r][c] = (Q[r,:] . K[c,:]) / sqrt(D); r = ty+16i, c = tx+16j
        {
            float racc[4][4];
            #pragma unroll
            for (int i = 0; i < 4; i++)
                #pragma unroll
                for (int j = 0; j < 4; j++) racc[i][j] = 0.f;

            #pragma unroll 4
            for (int k4 = 0; k4 < D; k4 += 4) {
                float4 qa[4], kb[4];
                #pragma unroll
                for (int i = 0; i < 4; i++)
                    qa[i] = *reinterpret_cast<const float4*>(&sm->Q[ty + 16 * i][k4]);
                #pragma unroll
                for (int j = 0; j < 4; j++)
                    kb[j] = *reinterpret_cast<const float4*>(&sm->Kt[tx + 16 * j][k4]);
                #pragma unroll
                for (int i = 0; i < 4; i++)
                    #pragma unroll
                    for (int j = 0; j < 4; j++) {
                        racc[i][j] = fmaf(qa[i].x, kb[j].x, racc[i][j]);
                        racc[i][j] = fmaf(qa[i].y, kb[j].y, racc[i][j]);
                        racc[i][j] = fmaf(qa[i].z, kb[j].z, racc[i][j]);
                        racc[i][j] = fmaf(qa[i].w, kb[j].w, racc[i][j]);
                    }
            }
            const float sc = 0.08838834764831845f;  // 1/sqrt(128)
            #pragma unroll
            for (int i = 0; i < 4; i++)
                #pragma unroll
                for (int j = 0; j < 4; j++)
                    sm->S[ty + 16 * i][tx + 16 * j] = racc[i][j] * sc;
        }
        __syncthreads();

        // Online softmax: thread -> row r = tid>>2, col block (tid&3)*16
        {
            int r     = tid >> 2;
            int part  = tid & 3;
            int row_g = qb + r;
            float vals[16];
            float mx = -INFINITY;
            #pragma unroll
            for (int c = 0; c < 16; c++) {
                int cc = part * 16 + c;
                float s = sm->S[r][cc];
                s = ((kt * BC + cc) <= row_g) ? s : -INFINITY;
                vals[c] = s;
                mx = fmaxf(mx, s);
            }
            mx = fmaxf(mx, __shfl_xor_sync(0xFFFFFFFF, mx, 1));
            mx = fmaxf(mx, __shfl_xor_sync(0xFFFFFFFF, mx, 2));
            float m_old = sm->m[r];
            float m_new = fmaxf(m_old, mx);
            float sum = 0.f;
            #pragma unroll
            for (int c = 0; c < 16; c++) {
                float p = __expf(vals[c] - m_new);
                sm->S[r][part * 16 + c] = p;
                sum += p;
            }
            sum += __shfl_xor_sync(0xFFFFFFFF, sum, 1);
            sum += __shfl_xor_sync(0xFFFFFFFF, sum, 2);
            if (part == 0) {
                float scl = __expf(m_old - m_new);
                sm->scale[r] = scl;
                sm->l[r] = sm->l[r] * scl + sum;
                sm->m[r] = m_new;
            }
        }
        __syncthreads();

        // acc rescale + P@V
        {
            float rs[4];
            #pragma unroll
            for (int i = 0; i < 4; i++) rs[i] = sm->scale[ty + 16 * i];
            #pragma unroll
            for (int i = 0; i < 4; i++)
                #pragma unroll
                for (int c = 0; c < 8; c++) acc[i][c] *= rs[i];

            #pragma unroll 2
            for (int j = 0; j < BC; j++) {
                float p[4];
                #pragma unroll
                for (int i = 0; i < 4; i++) p[i] = sm->S[ty + 16 * i][j];
                float vv[8];
                #pragma unroll
                for (int c = 0; c < 8; c++) vv[c] = sm->Vt[j][tx + 16 * c];
                #pragma unroll
                for (int i = 0; i < 4; i++)
                    #pragma unroll
                    for (int c = 0; c < 8; c++)
                        acc[i][c] = fmaf(p[i], vv[c], acc[i][c]);
            }
        }
    }
    __syncthreads();

    // Finalize: divide by l, write out
    {
        float rl[4];
        #pragma unroll
        for (int i = 0; i < 4; i++) rl[i] = 1.f / sm->l[ty + 16 * i];
        #pragma unroll
        for (int i = 0; i < 4; i++) {
            int r = qb + ty + 16 * i;
            #pragma unroll
            for (int c = 0; c < 8; c++)
                obase[(size_t)r * QDIM + tx + 16 * c] = acc[i][c] * rl[i];
        }
    }
}

// ---------------------------------------------------------------------------
// Launch
// ---------------------------------------------------------------------------
extern "C" void kernel_launch(void* const* d_in, const int* in_sizes, int n_in,
                              void* d_out, int out_size)
{
    const float* x   = (const float*)d_in[0];
    const float* wq  = (const float*)d_in[1];
    const float* bq  = (const float*)d_in[2];
    const float* wkv = (const float*)d_in[3];
    const float* bkv = (const float*)d_in[4];
    const float* wo  = (const float*)d_in[5];
    float* out = (float*)d_out;

    void *pq, *pkv, *patt;
    cudaGetSymbolAddress(&pq,   g_q);
    cudaGetSymbolAddress(&pkv,  g_kv);
    cudaGetSymbolAddress(&patt, g_att);

    // PE table
    pe_init_kernel<<<(T * D + 255) / 256, 256>>>();

    // Q projection (+bias +PE)
    {
        dim3 grid(QDIM / 128, MROWS / 128);
        sgemm_kernel<<<grid, 256>>>(x, wq, bq, (float*)pq, MROWS, QDIM, E, 1);
    }
    // KV projection (+bias +PE on K half)
    {
        dim3 grid(KVDIM / 128, MROWS / 128);
        sgemm_kernel<<<grid, 256>>>(x, wkv, bkv, (float*)pkv, MROWS, KVDIM, E, 2);
    }
    // Flash attention
    {
        size_t smem = sizeof(FlashSmem);
        cudaFuncSetAttribute(flash_kernel, cudaFuncAttributeMaxDynamicSharedMemorySize, (int)smem);
        dim3 grid(T / BR, NH, B);
        flash_kernel<<<grid, 256, smem>>>((const float*)pq, (const float*)pkv, (float*)patt);
    }
    // Output projection
    {
        dim3 grid(E / 128, MROWS / 128);
        sgemm_kernel<<<grid, 256>>>((const float*)patt, wo, nullptr, out, MROWS, E, QDIM, 0);
    }
}